// round 17
// baseline (speedup 1.0000x reference)
#include <cuda_runtime.h>

#define IN_DIM   8192
#define OUT_DIM  16384
#define TOPK     327
#define NBINS    9216            // 256 threads * 36 bins >= 8193
#define NTILES   16              // column tiles of 1024
#define NCTAS_PER_TILE 37        // 16 * 37 = 592 = 148 SMs * 4 CTAs
#define SEG      16              // rows per steal unit
#define NSEGS    (IN_DIM / SEG)  // 512 units per tile
#define CUT      (OUT_DIM - TOPK)   // 16057

// ------------- device scratch (loader zero-inits; kernel restores) -------
__device__ int g_overlap[OUT_DIM];
__device__ int g_hist[NBINS];
__device__ int g_seg[NTILES];    // per-tile steal counters
__device__ int g_tilecnt[NTILES];
__device__ int g_histdone;       // tiles whose histogram is complete
__device__ int g_donecnt;        // tiles whose output is written
__device__ int g_tie[OUT_DIM];
__device__ int g_ntie;

// ============ single fused kernel: GEMV + hist + topk + output ===========
// grid (NTILES, NCTAS_PER_TILE) = 592 CTAs, all co-resident (4/SM), so the
// inter-block spin barrier cannot deadlock.
// Phase 1: CTAs of tile T steal 16-row segments from g_seg[T] until empty;
//   active rows found by warp-0 ballot on x; 4 cols/thread accumulated in
//   registers across ALL stolen segments; one atomicAdd set at the end.
//   Dynamic stealing removes the binomial work imbalance of static splits
//   (the DRAM-idle drain that capped R15 at 60% dram_active).
// Phase 2 (16 tile-last blocks): histogram own 1024 finalized overlaps,
//   arrive on g_histdone, spin until all 16 tiles are in.
// Phase 3: redundant findT from the L2-resident histogram (shfl scan),
//   write own 1024-col output slice, zero-restore overlap, collect ties.
// Phase 4 (globally last block): resolve ties (lowest index wins — exact
//   jax.lax.top_k stability) and restore all scratch for the next replay.
__global__ void __launch_bounds__(256, 4) k_fused(const float* __restrict__ p,
                                                  const int* __restrict__ x,
                                                  float* __restrict__ out) {
    __shared__ int s_seg;
    __shared__ unsigned s_mask;
    __shared__ int s_last;
    __shared__ int warp_sums[8];
    __shared__ int sT, sNat;
    int t = threadIdx.x;
    int lane = t & 31, w = t >> 5;
    const int tile = blockIdx.x;
    const int col = tile * 1024 + t * 4;

    // ---- phase 1: work-stealing GEMV ----
    int a0 = 0, a1 = 0, a2 = 0, a3 = 0;
    for (;;) {
        if (t == 0) s_seg = atomicAdd(&g_seg[tile], 1);
        __syncthreads();
        int s = s_seg;
        if (s >= NSEGS) break;

        if (w == 0) {
            int xi = (lane < SEG) ? __ldg(&x[s * SEG + lane]) : 0;
            unsigned m = __ballot_sync(0xffffffffu, xi != 0);
            if (lane == 0) s_mask = m;
        }
        __syncthreads();
        unsigned m = s_mask;
        int base = s * SEG;
        while (m) {
            int b = __ffs(m) - 1;
            m &= m - 1;
            int rw = base + b;
            const float4 v = __ldg(reinterpret_cast<const float4*>(
                p + (size_t)rw * OUT_DIM + col));
            // jnp.round is half-to-even: round(0.5)=0 -> connection = (p > 0.5)
            a0 += (v.x > 0.5f);
            a1 += (v.y > 0.5f);
            a2 += (v.z > 0.5f);
            a3 += (v.w > 0.5f);
        }
    }
    if (a0 | a1 | a2 | a3) {
        atomicAdd(&g_overlap[col + 0], a0);
        atomicAdd(&g_overlap[col + 1], a1);
        atomicAdd(&g_overlap[col + 2], a2);
        atomicAdd(&g_overlap[col + 3], a3);
    }

    // ---- tile completion ----
    __threadfence();
    __syncthreads();
    if (t == 0) s_last = atomicAdd(&g_tilecnt[tile], 1);
    __syncthreads();
    if (s_last != NCTAS_PER_TILE - 1) return;   // 36 of 37 blocks exit here

    // ---- phase 2: histogram own finalized overlaps ----
    __threadfence();   // acquire: peer blocks' overlap atomics visible
    const int4 ov = *reinterpret_cast<const int4*>(&g_overlap[col]);
    atomicAdd(&g_hist[ov.x], 1);
    atomicAdd(&g_hist[ov.y], 1);
    atomicAdd(&g_hist[ov.z], 1);
    atomicAdd(&g_hist[ov.w], 1);

    // global barrier among the 16 surviving blocks
    __threadfence();
    __syncthreads();
    if (t == 0) {
        atomicAdd(&g_histdone, 1);
        while (atomicAdd(&g_histdone, 0) < NTILES) __nanosleep(100);
    }
    __syncthreads();
    __threadfence();   // acquire: all tiles' hist atomics visible

    // ---- phase 3a: redundant findT (36 bins/thread, shfl block scan) ----
    int v[36];
    {
        const int4* h4 = reinterpret_cast<const int4*>(g_hist);
        int b = t * 9;
        #pragma unroll
        for (int q = 0; q < 9; q++) {
            int4 hv = h4[b + q];
            v[q * 4 + 0] = hv.x; v[q * 4 + 1] = hv.y;
            v[q * 4 + 2] = hv.z; v[q * 4 + 3] = hv.w;
        }
    }
    int lsum = 0;
    #pragma unroll
    for (int j = 0; j < 36; j++) lsum += v[j];

    int incl = lsum;
    #pragma unroll
    for (int o = 1; o < 32; o <<= 1) {
        int s = __shfl_up_sync(0xffffffffu, incl, o);
        if (lane >= o) incl += s;
    }
    if (lane == 31) warp_sums[w] = incl;
    __syncthreads();
    if (w == 0 && lane < 8) {
        int ws = warp_sums[lane];
        int wincl = ws;
        #pragma unroll
        for (int o = 1; o < 8; o <<= 1) {
            int s = __shfl_up_sync(0x000000ffu, wincl, o);
            if (lane >= o) wincl += s;
        }
        warp_sums[lane] = wincl - ws;
    }
    __syncthreads();
    int run = incl - lsum + warp_sums[w];   // exclusive prefix

    {
        int b0 = t * 36;
        #pragma unroll
        for (int j = 0; j < 36; j++) {
            int h = v[j];
            if (run <= CUT && run + h > CUT) {
                sT   = b0 + j;
                sNat = TOPK - (OUT_DIM - (run + h));  // ties to take
            }
            run += h;
        }
    }
    __syncthreads();
    const int T = sT;
    const int nat = sNat;

    // ---- phase 3b: write output slice, restore overlap, collect ties ----
    *reinterpret_cast<int4*>(&g_overlap[col]) = make_int4(0, 0, 0, 0);
    float4 f;
    f.x = (ov.x > T) ? 1.0f : 0.0f;
    f.y = (ov.y > T) ? 1.0f : 0.0f;
    f.z = (ov.z > T) ? 1.0f : 0.0f;
    f.w = (ov.w > T) ? 1.0f : 0.0f;
    *reinterpret_cast<float4*>(out + col) = f;
    if (ov.x == T) { int q = atomicAdd(&g_ntie, 1); g_tie[q] = col + 0; }
    if (ov.y == T) { int q = atomicAdd(&g_ntie, 1); g_tie[q] = col + 1; }
    if (ov.z == T) { int q = atomicAdd(&g_ntie, 1); g_tie[q] = col + 2; }
    if (ov.w == T) { int q = atomicAdd(&g_ntie, 1); g_tie[q] = col + 3; }

    // ---- phase 4: globally last block resolves ties + restores scratch ----
    __threadfence();
    __syncthreads();
    if (t == 0) s_last = atomicAdd(&g_donecnt, 1);
    __syncthreads();
    if (s_last == NTILES - 1) {
        __threadfence();   // acquire: all blocks' g_tie writes visible
        int n = atomicAdd(&g_ntie, 0);
        for (int k = t; k < n; k += 256) {
            int idx = g_tie[k];
            int rank = 0;
            for (int j = 0; j < n; j++) rank += (g_tie[j] < idx);
            if (rank < nat) out[idx] = 1.0f;
        }
        // restore for next graph replay (loader guarantees zeros on call 0)
        int4* h4 = reinterpret_cast<int4*>(g_hist);
        for (int q = t; q < NBINS / 4; q += 256)
            h4[q] = make_int4(0, 0, 0, 0);
        if (t < NTILES) { g_tilecnt[t] = 0; g_seg[t] = 0; }
        if (t == 0) { g_histdone = 0; g_donecnt = 0; g_ntie = 0; }
    }
}

// ---------------- launch ----------------
extern "C" void kernel_launch(void* const* d_in, const int* in_sizes, int n_in,
                              void* d_out, int out_size) {
    const int*   x;
    const float* p;
    if (in_sizes[0] == IN_DIM) {
        x = (const int*)d_in[0];
        p = (const float*)d_in[1];
    } else {
        x = (const int*)d_in[1];
        p = (const float*)d_in[0];
    }

    k_fused<<<dim3(NTILES, NCTAS_PER_TILE), 256>>>(p, x, (float*)d_out);
}